// round 2
// baseline (speedup 1.0000x reference)
#include <cuda_runtime.h>
#include <math.h>

#define N_NODES 50000
#define N_FEAT  128
#define N_EDGES 800000

// Scratch (allocation-free rule: __device__ globals)
__device__ float g_h[N_NODES * N_FEAT];   // per-layer linear output
__device__ float g_x[N_NODES * N_FEAT];   // layer-0 aggregate (pre-ELU; ELU fused into layer-1 GEMM load)

// ---------------------------------------------------------------------------
// GEMM: H[n][j] = sum_k act(X[n][k]) * W[k][j] + B[j]
// act = identity or ELU (fused on the X-tile load).
// Tile: 64 rows x 128 cols per block, full K=128. 256 threads.
// Each thread: 8 rows x 4 cols of output. X-tile + W fully in smem (96 KB).
// ---------------------------------------------------------------------------
template <bool ELU_IN>
__global__ __launch_bounds__(256) void gemm_kernel(
    const float* __restrict__ X, const float* __restrict__ W,
    const float* __restrict__ B, float* __restrict__ H)
{
    extern __shared__ float smem[];
    float* As = smem;               // [64][128]
    float* Ws = smem + 64 * 128;    // [128][128]

    const int tid = threadIdx.x;
    const int rowBase = blockIdx.x * 64;

    // Load W (128x128) into smem, vectorized
    const float4* W4 = (const float4*)W;
    float4* Ws4 = (float4*)Ws;
    #pragma unroll
    for (int i = tid; i < 128 * 32; i += 256) Ws4[i] = W4[i];

    // Load X tile (64x128), zero-pad past N_NODES, optional fused ELU
    float4* As4 = (float4*)As;
    #pragma unroll
    for (int i = tid; i < 64 * 32; i += 256) {
        int r = i >> 5, c4 = i & 31;
        int gr = rowBase + r;
        float4 v = make_float4(0.f, 0.f, 0.f, 0.f);
        if (gr < N_NODES) v = ((const float4*)X)[gr * 32 + c4];
        if (ELU_IN) {
            v.x = v.x > 0.f ? v.x : expm1f(v.x);
            v.y = v.y > 0.f ? v.y : expm1f(v.y);
            v.z = v.z > 0.f ? v.z : expm1f(v.z);
            v.w = v.w > 0.f ? v.w : expm1f(v.w);
        }
        As4[i] = v;
    }
    __syncthreads();

    const int warp = tid >> 5, lane = tid & 31;
    const int r0 = warp * 8;       // local row base
    const int c0 = lane * 4;       // col base

    float acc[8][4];
    #pragma unroll
    for (int i = 0; i < 8; i++)
        #pragma unroll
        for (int j = 0; j < 4; j++) acc[i][j] = 0.f;

    #pragma unroll 4
    for (int k = 0; k < 128; k++) {
        float4 w = *(const float4*)&Ws[k * 128 + c0];
        #pragma unroll
        for (int i = 0; i < 8; i++) {
            float a = As[(r0 + i) * 128 + k];
            acc[i][0] += a * w.x;
            acc[i][1] += a * w.y;
            acc[i][2] += a * w.z;
            acc[i][3] += a * w.w;
        }
    }

    float4 bb = *(const float4*)&B[c0];
    #pragma unroll
    for (int i = 0; i < 8; i++) {
        int gr = rowBase + r0 + i;
        if (gr < N_NODES) {
            float4 o = make_float4(acc[i][0] + bb.x, acc[i][1] + bb.y,
                                   acc[i][2] + bb.z, acc[i][3] + bb.w);
            ((float4*)H)[gr * 32 + (c0 >> 2)] = o;
        }
    }
}

// ---------------------------------------------------------------------------
// Scatter: out[row] += val * H[col], one warp per edge, vector reduction.
// red.global.add.v4.f32: 16B-aligned (row*512B + lane*16B), no return value.
// ---------------------------------------------------------------------------
__global__ __launch_bounds__(512) void scatter_kernel(
    const int* __restrict__ rows, const int* __restrict__ cols,
    const float* __restrict__ vals, const float* __restrict__ H,
    float* __restrict__ out)
{
    int gw = (blockIdx.x * blockDim.x + threadIdx.x) >> 5;
    int lane = threadIdx.x & 31;
    if (gw >= N_EDGES) return;

    int r = rows[gw];
    int c = cols[gw];
    float v = vals[gw];

    float4 hv = ((const float4*)H)[c * 32 + lane];
    float4 m = make_float4(hv.x * v, hv.y * v, hv.z * v, hv.w * v);
    float* dst = out + (size_t)r * 128 + lane * 4;
    asm volatile("red.global.add.v4.f32 [%0], {%1,%2,%3,%4};"
                 :: "l"(dst), "f"(m.x), "f"(m.y), "f"(m.z), "f"(m.w)
                 : "memory");
}

// ---------------------------------------------------------------------------
// ELU (elementwise): y = x>0 ? x : expm1(x). Used only on the final output.
// ---------------------------------------------------------------------------
__global__ __launch_bounds__(256) void elu_kernel(
    const float* __restrict__ in, float* __restrict__ out, int n4)
{
    int i = blockIdx.x * blockDim.x + threadIdx.x;
    if (i >= n4) return;
    float4 v = ((const float4*)in)[i];
    v.x = v.x > 0.f ? v.x : expm1f(v.x);
    v.y = v.y > 0.f ? v.y : expm1f(v.y);
    v.z = v.z > 0.f ? v.z : expm1f(v.z);
    v.w = v.w > 0.f ? v.w : expm1f(v.w);
    ((float4*)out)[i] = v;
}

extern "C" void kernel_launch(void* const* d_in, const int* in_sizes, int n_in,
                              void* d_out, int out_size)
{
    const float* x    = (const float*)d_in[0];   // [50000,128]
    const float* W    = (const float*)d_in[1];   // [2,128,128]
    const float* b    = (const float*)d_in[2];   // [2,128]
    const int*   rows = (const int*)d_in[3];     // [2,800000]
    const int*   cols = (const int*)d_in[4];     // [2,800000]
    const float* vals = (const float*)d_in[5];   // [2,800000]
    float* out = (float*)d_out;                  // [50000,128]

    float *h_ptr, *x_ptr;
    cudaGetSymbolAddress((void**)&h_ptr, g_h);
    cudaGetSymbolAddress((void**)&x_ptr, g_x);

    const size_t feat_bytes = (size_t)N_NODES * N_FEAT * sizeof(float);
    const int gemm_smem = (64 * 128 + 128 * 128) * sizeof(float);  // 96 KB
    cudaFuncSetAttribute(gemm_kernel<false>,
                         cudaFuncAttributeMaxDynamicSharedMemorySize, gemm_smem);
    cudaFuncSetAttribute(gemm_kernel<true>,
                         cudaFuncAttributeMaxDynamicSharedMemorySize, gemm_smem);

    const int gemm_grid    = (N_NODES + 63) / 64;
    const int scatter_grid = (N_EDGES + 15) / 16;      // 16 warps/block of 512
    const int n4           = N_NODES * N_FEAT / 4;
    const int elu_grid     = (n4 + 255) / 256;

    // ---- Layer 0 ----
    gemm_kernel<false><<<gemm_grid, 256, gemm_smem>>>(x, W, b, h_ptr);
    cudaMemsetAsync(x_ptr, 0, feat_bytes);
    scatter_kernel<<<scatter_grid, 512>>>(rows, cols, vals, h_ptr, x_ptr);
    // (no ELU pass: fused into the layer-1 GEMM X load)

    // ---- Layer 1 ----
    gemm_kernel<true><<<gemm_grid, 256, gemm_smem>>>(x_ptr, W + 128 * 128,
                                                     b + 128, h_ptr);
    cudaMemsetAsync(out, 0, feat_bytes);
    scatter_kernel<<<scatter_grid, 512>>>(rows + N_EDGES, cols + N_EDGES,
                                          vals + N_EDGES, h_ptr, out);
    elu_kernel<<<elu_grid, 256>>>(out, out, n4);
}

// round 3
// speedup vs baseline: 1.4772x; 1.4772x over previous
#include <cuda_runtime.h>
#include <math.h>

#define N_NODES 50000
#define N_FEAT  128
#define N_EDGES 800000

#define SCAN_B   512
#define SCAN_NB  ((N_NODES + SCAN_B - 1) / SCAN_B)   // 98

// ---- Scratch (allocation-free rule: __device__ globals) ----
__device__ float g_h[N_NODES * N_FEAT];   // per-layer linear output
__device__ float g_x[N_NODES * N_FEAT];   // layer-0 activation
__device__ int   g_cnt[N_NODES];          // histogram counts
__device__ int   g_off[N_NODES];          // exclusive CSR offsets
__device__ int   g_cur[N_NODES];          // bucket cursors
__device__ int   g_bsum[128];             // scan block sums (>= SCAN_NB)
__device__ int   g_scol[N_EDGES];         // cols sorted by dest row
__device__ float g_sval[N_EDGES];         // vals sorted by dest row

// ---------------------------------------------------------------------------
// GEMM: H[n][j] = sum_k X[n][k] * W[k][j] + B[j]
// 64x128 tile, full K in smem (96 KB). k stepped by 4 with float4 As loads
// (warp-uniform broadcast) -> 12 LDS.128 per 128 FFMA per thread.
// ---------------------------------------------------------------------------
__global__ __launch_bounds__(256) void gemm_kernel(
    const float* __restrict__ X, const float* __restrict__ W,
    const float* __restrict__ B, float* __restrict__ H)
{
    extern __shared__ float smem[];
    float* As = smem;               // [64][128]
    float* Ws = smem + 64 * 128;    // [128][128]
    float4* As4 = (float4*)As;

    const int tid = threadIdx.x;
    const int rowBase = blockIdx.x * 64;

    const float4* W4 = (const float4*)W;
    float4* Ws4 = (float4*)Ws;
    #pragma unroll
    for (int i = tid; i < 128 * 32; i += 256) Ws4[i] = W4[i];

    #pragma unroll
    for (int i = tid; i < 64 * 32; i += 256) {
        int r = i >> 5, c4 = i & 31;
        int gr = rowBase + r;
        float4 v = make_float4(0.f, 0.f, 0.f, 0.f);
        if (gr < N_NODES) v = ((const float4*)X)[gr * 32 + c4];
        As4[i] = v;
    }
    __syncthreads();

    const int warp = tid >> 5, lane = tid & 31;
    const int r0 = warp * 8;       // local row base
    const int c0 = lane * 4;       // col base

    float acc[8][4];
    #pragma unroll
    for (int i = 0; i < 8; i++)
        #pragma unroll
        for (int j = 0; j < 4; j++) acc[i][j] = 0.f;

    #pragma unroll 2
    for (int k4 = 0; k4 < 32; k4++) {
        float4 a[8];
        #pragma unroll
        for (int i = 0; i < 8; i++) a[i] = As4[(r0 + i) * 32 + k4];  // broadcast

        #pragma unroll
        for (int kk = 0; kk < 4; kk++) {
            float4 w = *(const float4*)&Ws[(k4 * 4 + kk) * 128 + c0];
            #pragma unroll
            for (int i = 0; i < 8; i++) {
                float av = (kk == 0) ? a[i].x : (kk == 1) ? a[i].y
                         : (kk == 2) ? a[i].z : a[i].w;
                acc[i][0] += av * w.x;
                acc[i][1] += av * w.y;
                acc[i][2] += av * w.z;
                acc[i][3] += av * w.w;
            }
        }
    }

    float4 bb = *(const float4*)&B[c0];
    #pragma unroll
    for (int i = 0; i < 8; i++) {
        int gr = rowBase + r0 + i;
        if (gr < N_NODES) {
            float4 o = make_float4(acc[i][0] + bb.x, acc[i][1] + bb.y,
                                   acc[i][2] + bb.z, acc[i][3] + bb.w);
            ((float4*)H)[gr * 32 + (c0 >> 2)] = o;
        }
    }
}

// ---------------------------------------------------------------------------
// CSR build: histogram -> 3-kernel exclusive scan -> bucket (counting sort)
// ---------------------------------------------------------------------------
__global__ __launch_bounds__(256) void hist_kernel(const int* __restrict__ rows)
{
    int e = blockIdx.x * blockDim.x + threadIdx.x;
    if (e < N_EDGES) atomicAdd(&g_cnt[rows[e]], 1);
}

__global__ __launch_bounds__(SCAN_B) void scan1_kernel()
{
    __shared__ int s[SCAN_B];
    int i = blockIdx.x * SCAN_B + threadIdx.x;
    int v = (i < N_NODES) ? g_cnt[i] : 0;
    s[threadIdx.x] = v;
    __syncthreads();
    #pragma unroll
    for (int d = 1; d < SCAN_B; d <<= 1) {
        int t = (threadIdx.x >= d) ? s[threadIdx.x - d] : 0;
        __syncthreads();
        s[threadIdx.x] += t;
        __syncthreads();
    }
    if (i < N_NODES) g_off[i] = s[threadIdx.x] - v;     // exclusive in-block
    if (threadIdx.x == SCAN_B - 1) g_bsum[blockIdx.x] = s[SCAN_B - 1];
}

__global__ __launch_bounds__(128) void scan2_kernel()
{
    __shared__ int s[128];
    int t = threadIdx.x;
    int v = (t < SCAN_NB) ? g_bsum[t] : 0;
    s[t] = v;
    __syncthreads();
    #pragma unroll
    for (int d = 1; d < 128; d <<= 1) {
        int u = (t >= d) ? s[t - d] : 0;
        __syncthreads();
        s[t] += u;
        __syncthreads();
    }
    if (t < SCAN_NB) g_bsum[t] = s[t] - v;              // exclusive
}

__global__ __launch_bounds__(SCAN_B) void scan3_kernel()
{
    int i = blockIdx.x * SCAN_B + threadIdx.x;
    if (i < N_NODES) {
        int o = g_off[i] + g_bsum[blockIdx.x];
        g_off[i] = o;
        g_cur[i] = o;
    }
}

__global__ __launch_bounds__(256) void bucket_kernel(
    const int* __restrict__ rows, const int* __restrict__ cols,
    const float* __restrict__ vals)
{
    int e = blockIdx.x * blockDim.x + threadIdx.x;
    if (e < N_EDGES) {
        int p = atomicAdd(&g_cur[rows[e]], 1);
        g_scol[p] = cols[e];
        g_sval[p] = vals[e];
    }
}

// ---------------------------------------------------------------------------
// Aggregate: one warp per node; register accumulation over its CSR segment;
// fused ELU epilogue. No atomics, no output memset needed.
// ---------------------------------------------------------------------------
__global__ __launch_bounds__(256) void aggregate_kernel(
    const float* __restrict__ H, float* __restrict__ out)
{
    int w = (blockIdx.x * blockDim.x + threadIdx.x) >> 5;
    int lane = threadIdx.x & 31;
    if (w >= N_NODES) return;

    int beg = g_off[w];
    int end = (w == N_NODES - 1) ? N_EDGES : g_off[w + 1];

    float4 acc = make_float4(0.f, 0.f, 0.f, 0.f);
    for (int j = beg; j < end; j++) {
        int   c = g_scol[j];           // warp-uniform broadcast load
        float v = g_sval[j];
        float4 hv = ((const float4*)H)[c * 32 + lane];
        acc.x += v * hv.x;
        acc.y += v * hv.y;
        acc.z += v * hv.z;
        acc.w += v * hv.w;
    }
    acc.x = acc.x > 0.f ? acc.x : expm1f(acc.x);
    acc.y = acc.y > 0.f ? acc.y : expm1f(acc.y);
    acc.z = acc.z > 0.f ? acc.z : expm1f(acc.z);
    acc.w = acc.w > 0.f ? acc.w : expm1f(acc.w);
    ((float4*)out)[w * 32 + lane] = acc;
}

extern "C" void kernel_launch(void* const* d_in, const int* in_sizes, int n_in,
                              void* d_out, int out_size)
{
    const float* x    = (const float*)d_in[0];   // [50000,128]
    const float* W    = (const float*)d_in[1];   // [2,128,128]
    const float* b    = (const float*)d_in[2];   // [2,128]
    const int*   rows = (const int*)d_in[3];     // [2,800000]
    const int*   cols = (const int*)d_in[4];     // [2,800000]
    const float* vals = (const float*)d_in[5];   // [2,800000]
    float* out = (float*)d_out;                  // [50000,128]

    float *h_ptr, *x_ptr;
    int   *cnt_ptr;
    cudaGetSymbolAddress((void**)&h_ptr, g_h);
    cudaGetSymbolAddress((void**)&x_ptr, g_x);
    cudaGetSymbolAddress((void**)&cnt_ptr, g_cnt);

    const int gemm_smem = (64 * 128 + 128 * 128) * sizeof(float);  // 96 KB
    cudaFuncSetAttribute(gemm_kernel,
                         cudaFuncAttributeMaxDynamicSharedMemorySize, gemm_smem);

    const int gemm_grid = (N_NODES + 63) / 64;
    const int edge_grid = (N_EDGES + 255) / 256;
    const int agg_grid  = (N_NODES * 32 + 255) / 256;   // warp per node

    for (int l = 0; l < 2; l++) {
        const float* xin  = (l == 0) ? x : x_ptr;
        float*       xout = (l == 0) ? x_ptr : out;
        const int*   rl = rows + (size_t)l * N_EDGES;
        const int*   cl = cols + (size_t)l * N_EDGES;
        const float* vl = vals + (size_t)l * N_EDGES;

        // Dense: h = xin @ W[l] + b[l]
        gemm_kernel<<<gemm_grid, 256, gemm_smem>>>(
            xin, W + (size_t)l * 128 * 128, b + (size_t)l * 128, h_ptr);

        // CSR build (counting sort by destination row)
        cudaMemsetAsync(cnt_ptr, 0, N_NODES * sizeof(int));
        hist_kernel<<<edge_grid, 256>>>(rl);
        scan1_kernel<<<SCAN_NB, SCAN_B>>>();
        scan2_kernel<<<1, 128>>>();
        scan3_kernel<<<SCAN_NB, SCAN_B>>>();
        bucket_kernel<<<edge_grid, 256>>>(rl, cl, vl);

        // Gather-reduce + fused ELU
        aggregate_kernel<<<agg_grid, 256>>>(h_ptr, xout);
    }
}

// round 4
// speedup vs baseline: 1.4840x; 1.0046x over previous
#include <cuda_runtime.h>
#include <math.h>

#define N_NODES 50000
#define N_FEAT  128
#define N_EDGES 800000

#define SCAN_B   512
#define SCAN_NB  ((N_NODES + SCAN_B - 1) / SCAN_B)   // 98

// ---- Scratch (allocation-free rule: __device__ globals) ----
__device__ float g_h[N_NODES * N_FEAT];   // per-layer linear output
__device__ float g_x[N_NODES * N_FEAT];   // layer-0 activation
__device__ int   g_cnt[N_NODES];          // histogram counts
__device__ int   g_off[N_NODES];          // exclusive CSR offsets
__device__ int   g_cur[N_NODES];          // bucket cursors
__device__ int   g_bsum[128];             // scan block sums (>= SCAN_NB)
__device__ int   g_scol[N_EDGES];         // cols sorted by dest row
__device__ float g_sval[N_EDGES];         // vals sorted by dest row

// ---------------------------------------------------------------------------
// GEMM: H[n][j] = sum_k X[n][k] * W[k][j] + B[j]
// 64x128 tile, full K in smem (96 KB). k stepped by 4 with float4 As loads
// (warp-uniform broadcast) -> 12 LDS.128 per 128 FFMA per thread.
// ---------------------------------------------------------------------------
__global__ __launch_bounds__(256) void gemm_kernel(
    const float* __restrict__ X, const float* __restrict__ W,
    const float* __restrict__ B, float* __restrict__ H)
{
    extern __shared__ float smem[];
    float* As = smem;               // [64][128]
    float* Ws = smem + 64 * 128;    // [128][128]
    float4* As4 = (float4*)As;

    const int tid = threadIdx.x;
    const int rowBase = blockIdx.x * 64;

    const float4* W4 = (const float4*)W;
    float4* Ws4 = (float4*)Ws;
    #pragma unroll
    for (int i = tid; i < 128 * 32; i += 256) Ws4[i] = W4[i];

    #pragma unroll
    for (int i = tid; i < 64 * 32; i += 256) {
        int r = i >> 5, c4 = i & 31;
        int gr = rowBase + r;
        float4 v = make_float4(0.f, 0.f, 0.f, 0.f);
        if (gr < N_NODES) v = ((const float4*)X)[gr * 32 + c4];
        As4[i] = v;
    }
    __syncthreads();

    const int warp = tid >> 5, lane = tid & 31;
    const int r0 = warp * 8;       // local row base
    const int c0 = lane * 4;       // col base

    float acc[8][4];
    #pragma unroll
    for (int i = 0; i < 8; i++)
        #pragma unroll
        for (int j = 0; j < 4; j++) acc[i][j] = 0.f;

    #pragma unroll 2
    for (int k4 = 0; k4 < 32; k4++) {
        float4 a[8];
        #pragma unroll
        for (int i = 0; i < 8; i++) a[i] = As4[(r0 + i) * 32 + k4];  // broadcast

        #pragma unroll
        for (int kk = 0; kk < 4; kk++) {
            float4 w = *(const float4*)&Ws[(k4 * 4 + kk) * 128 + c0];
            #pragma unroll
            for (int i = 0; i < 8; i++) {
                float av = (kk == 0) ? a[i].x : (kk == 1) ? a[i].y
                         : (kk == 2) ? a[i].z : a[i].w;
                acc[i][0] += av * w.x;
                acc[i][1] += av * w.y;
                acc[i][2] += av * w.z;
                acc[i][3] += av * w.w;
            }
        }
    }

    float4 bb = *(const float4*)&B[c0];
    #pragma unroll
    for (int i = 0; i < 8; i++) {
        int gr = rowBase + r0 + i;
        if (gr < N_NODES) {
            float4 o = make_float4(acc[i][0] + bb.x, acc[i][1] + bb.y,
                                   acc[i][2] + bb.z, acc[i][3] + bb.w);
            ((float4*)H)[gr * 32 + (c0 >> 2)] = o;
        }
    }
}

// ---------------------------------------------------------------------------
// CSR build: histogram -> 3-kernel exclusive scan -> bucket (counting sort)
// ---------------------------------------------------------------------------
__global__ __launch_bounds__(256) void hist_kernel(const int* __restrict__ rows)
{
    int e = blockIdx.x * blockDim.x + threadIdx.x;
    if (e < N_EDGES) atomicAdd(&g_cnt[rows[e]], 1);
}

__global__ __launch_bounds__(SCAN_B) void scan1_kernel()
{
    __shared__ int s[SCAN_B];
    int i = blockIdx.x * SCAN_B + threadIdx.x;
    int v = (i < N_NODES) ? g_cnt[i] : 0;
    s[threadIdx.x] = v;
    __syncthreads();
    #pragma unroll
    for (int d = 1; d < SCAN_B; d <<= 1) {
        int t = (threadIdx.x >= d) ? s[threadIdx.x - d] : 0;
        __syncthreads();
        s[threadIdx.x] += t;
        __syncthreads();
    }
    if (i < N_NODES) g_off[i] = s[threadIdx.x] - v;     // exclusive in-block
    if (threadIdx.x == SCAN_B - 1) g_bsum[blockIdx.x] = s[SCAN_B - 1];
}

__global__ __launch_bounds__(128) void scan2_kernel()
{
    __shared__ int s[128];
    int t = threadIdx.x;
    int v = (t < SCAN_NB) ? g_bsum[t] : 0;
    s[t] = v;
    __syncthreads();
    #pragma unroll
    for (int d = 1; d < 128; d <<= 1) {
        int u = (t >= d) ? s[t - d] : 0;
        __syncthreads();
        s[t] += u;
        __syncthreads();
    }
    if (t < SCAN_NB) g_bsum[t] = s[t] - v;              // exclusive
}

__global__ __launch_bounds__(SCAN_B) void scan3_kernel()
{
    int i = blockIdx.x * SCAN_B + threadIdx.x;
    if (i < N_NODES) {
        int o = g_off[i] + g_bsum[blockIdx.x];
        g_off[i] = o;
        g_cur[i] = o;
    }
}

__global__ __launch_bounds__(256) void bucket_kernel(
    const int* __restrict__ rows, const int* __restrict__ cols,
    const float* __restrict__ vals)
{
    int e = blockIdx.x * blockDim.x + threadIdx.x;
    if (e < N_EDGES) {
        int p = atomicAdd(&g_cur[rows[e]], 1);
        g_scol[p] = cols[e];
        g_sval[p] = vals[e];
    }
}

// ---------------------------------------------------------------------------
// Aggregate: one warp per node; register accumulation over its CSR segment;
// fused ELU epilogue. No atomics, no output memset needed.
// ---------------------------------------------------------------------------
__global__ __launch_bounds__(256) void aggregate_kernel(
    const float* __restrict__ H, float* __restrict__ out)
{
    int w = (blockIdx.x * blockDim.x + threadIdx.x) >> 5;
    int lane = threadIdx.x & 31;
    if (w >= N_NODES) return;

    int beg = g_off[w];
    int end = (w == N_NODES - 1) ? N_EDGES : g_off[w + 1];

    float4 acc = make_float4(0.f, 0.f, 0.f, 0.f);
    for (int j = beg; j < end; j++) {
        int   c = g_scol[j];           // warp-uniform broadcast load
        float v = g_sval[j];
        float4 hv = ((const float4*)H)[c * 32 + lane];
        acc.x += v * hv.x;
        acc.y += v * hv.y;
        acc.z += v * hv.z;
        acc.w += v * hv.w;
    }
    acc.x = acc.x > 0.f ? acc.x : expm1f(acc.x);
    acc.y = acc.y > 0.f ? acc.y : expm1f(acc.y);
    acc.z = acc.z > 0.f ? acc.z : expm1f(acc.z);
    acc.w = acc.w > 0.f ? acc.w : expm1f(acc.w);
    ((float4*)out)[w * 32 + lane] = acc;
}

extern "C" void kernel_launch(void* const* d_in, const int* in_sizes, int n_in,
                              void* d_out, int out_size)
{
    const float* x    = (const float*)d_in[0];   // [50000,128]
    const float* W    = (const float*)d_in[1];   // [2,128,128]
    const float* b    = (const float*)d_in[2];   // [2,128]
    const int*   rows = (const int*)d_in[3];     // [2,800000]
    const int*   cols = (const int*)d_in[4];     // [2,800000]
    const float* vals = (const float*)d_in[5];   // [2,800000]
    float* out = (float*)d_out;                  // [50000,128]

    float *h_ptr, *x_ptr;
    int   *cnt_ptr;
    cudaGetSymbolAddress((void**)&h_ptr, g_h);
    cudaGetSymbolAddress((void**)&x_ptr, g_x);
    cudaGetSymbolAddress((void**)&cnt_ptr, g_cnt);

    const int gemm_smem = (64 * 128 + 128 * 128) * sizeof(float);  // 96 KB
    cudaFuncSetAttribute(gemm_kernel,
                         cudaFuncAttributeMaxDynamicSharedMemorySize, gemm_smem);

    const int gemm_grid = (N_NODES + 63) / 64;
    const int edge_grid = (N_EDGES + 255) / 256;
    const int agg_grid  = (N_NODES * 32 + 255) / 256;   // warp per node

    for (int l = 0; l < 2; l++) {
        const float* xin  = (l == 0) ? x : x_ptr;
        float*       xout = (l == 0) ? x_ptr : out;
        const int*   rl = rows + (size_t)l * N_EDGES;
        const int*   cl = cols + (size_t)l * N_EDGES;
        const float* vl = vals + (size_t)l * N_EDGES;

        // Dense: h = xin @ W[l] + b[l]
        gemm_kernel<<<gemm_grid, 256, gemm_smem>>>(
            xin, W + (size_t)l * 128 * 128, b + (size_t)l * 128, h_ptr);

        // CSR build (counting sort by destination row)
        cudaMemsetAsync(cnt_ptr, 0, N_NODES * sizeof(int));
        hist_kernel<<<edge_grid, 256>>>(rl);
        scan1_kernel<<<SCAN_NB, SCAN_B>>>();
        scan2_kernel<<<1, 128>>>();
        scan3_kernel<<<SCAN_NB, SCAN_B>>>();
        bucket_kernel<<<edge_grid, 256>>>(rl, cl, vl);

        // Gather-reduce + fused ELU
        aggregate_kernel<<<agg_grid, 256>>>(h_ptr, xout);
    }
}

// round 5
// speedup vs baseline: 1.6449x; 1.1084x over previous
#include <cuda_runtime.h>
#include <math.h>

#define N_NODES 50000
#define N_FEAT  128
#define N_EDGES 800000

#define SCAN_B   512
#define SCAN_NB  ((N_NODES + SCAN_B - 1) / SCAN_B)   // 98

// ---- Scratch (allocation-free rule: __device__ globals); per-layer CSR sets ----
__device__ float g_h[N_NODES * N_FEAT];       // per-layer linear output
__device__ float g_x[N_NODES * N_FEAT];       // layer-0 activation
__device__ int   g_cnt [2][N_NODES];
__device__ int   g_off [2][N_NODES + 1];      // +1: sentinel end = N_EDGES
__device__ int   g_cur [2][N_NODES];
__device__ int   g_bsum[2][128];
__device__ int   g_scol[2][N_EDGES];
__device__ float g_sval[2][N_EDGES];

// ---- Streams/events for capture-time fork/join (created once, no device mem APIs)
static cudaStream_t s_csr[2];
static cudaEvent_t  ev_fork, ev_done[2];
static bool s_async_ok = false;
struct AsyncInit {
    AsyncInit() {
        bool ok = true;
        ok &= cudaStreamCreateWithFlags(&s_csr[0], cudaStreamNonBlocking) == cudaSuccess;
        ok &= cudaStreamCreateWithFlags(&s_csr[1], cudaStreamNonBlocking) == cudaSuccess;
        ok &= cudaEventCreateWithFlags(&ev_fork,    cudaEventDisableTiming) == cudaSuccess;
        ok &= cudaEventCreateWithFlags(&ev_done[0], cudaEventDisableTiming) == cudaSuccess;
        ok &= cudaEventCreateWithFlags(&ev_done[1], cudaEventDisableTiming) == cudaSuccess;
        s_async_ok = ok;
    }
};
static AsyncInit s_async_init;

// ---------------------------------------------------------------------------
// GEMM: H[n][j] = sum_k X[n][k] * W[k][j] + B[j]
// 64x128 tile, full K in smem (96 KB). k stepped by 4 with float4 As loads.
// ---------------------------------------------------------------------------
__global__ __launch_bounds__(256) void gemm_kernel(
    const float* __restrict__ X, const float* __restrict__ W,
    const float* __restrict__ B, float* __restrict__ H)
{
    extern __shared__ float smem[];
    float* As = smem;               // [64][128]
    float* Ws = smem + 64 * 128;    // [128][128]
    float4* As4 = (float4*)As;

    const int tid = threadIdx.x;
    const int rowBase = blockIdx.x * 64;

    const float4* W4 = (const float4*)W;
    float4* Ws4 = (float4*)Ws;
    #pragma unroll
    for (int i = tid; i < 128 * 32; i += 256) Ws4[i] = W4[i];

    #pragma unroll
    for (int i = tid; i < 64 * 32; i += 256) {
        int r = i >> 5, c4 = i & 31;
        int gr = rowBase + r;
        float4 v = make_float4(0.f, 0.f, 0.f, 0.f);
        if (gr < N_NODES) v = ((const float4*)X)[gr * 32 + c4];
        As4[i] = v;
    }
    __syncthreads();

    const int warp = tid >> 5, lane = tid & 31;
    const int r0 = warp * 8;
    const int c0 = lane * 4;

    float acc[8][4];
    #pragma unroll
    for (int i = 0; i < 8; i++)
        #pragma unroll
        for (int j = 0; j < 4; j++) acc[i][j] = 0.f;

    #pragma unroll 2
    for (int k4 = 0; k4 < 32; k4++) {
        float4 a[8];
        #pragma unroll
        for (int i = 0; i < 8; i++) a[i] = As4[(r0 + i) * 32 + k4];  // broadcast

        #pragma unroll
        for (int kk = 0; kk < 4; kk++) {
            float4 w = *(const float4*)&Ws[(k4 * 4 + kk) * 128 + c0];
            #pragma unroll
            for (int i = 0; i < 8; i++) {
                float av = (kk == 0) ? a[i].x : (kk == 1) ? a[i].y
                         : (kk == 2) ? a[i].z : a[i].w;
                acc[i][0] += av * w.x;
                acc[i][1] += av * w.y;
                acc[i][2] += av * w.z;
                acc[i][3] += av * w.w;
            }
        }
    }

    float4 bb = *(const float4*)&B[c0];
    #pragma unroll
    for (int i = 0; i < 8; i++) {
        int gr = rowBase + r0 + i;
        if (gr < N_NODES) {
            float4 o = make_float4(acc[i][0] + bb.x, acc[i][1] + bb.y,
                                   acc[i][2] + bb.z, acc[i][3] + bb.w);
            ((float4*)H)[gr * 32 + (c0 >> 2)] = o;
        }
    }
}

// ---------------------------------------------------------------------------
// CSR build: histogram -> 3-kernel exclusive scan -> bucket (counting sort)
// ---------------------------------------------------------------------------
__global__ __launch_bounds__(256) void hist_kernel(
    const int* __restrict__ rows, int* __restrict__ cnt)
{
    int e = blockIdx.x * blockDim.x + threadIdx.x;
    if (e < N_EDGES) atomicAdd(&cnt[rows[e]], 1);
}

__global__ __launch_bounds__(SCAN_B) void scan1_kernel(
    const int* __restrict__ cnt, int* __restrict__ off, int* __restrict__ bsum)
{
    __shared__ int s[SCAN_B];
    int i = blockIdx.x * SCAN_B + threadIdx.x;
    int v = (i < N_NODES) ? cnt[i] : 0;
    s[threadIdx.x] = v;
    __syncthreads();
    #pragma unroll
    for (int d = 1; d < SCAN_B; d <<= 1) {
        int t = (threadIdx.x >= d) ? s[threadIdx.x - d] : 0;
        __syncthreads();
        s[threadIdx.x] += t;
        __syncthreads();
    }
    if (i < N_NODES) off[i] = s[threadIdx.x] - v;       // exclusive in-block
    if (threadIdx.x == SCAN_B - 1) bsum[blockIdx.x] = s[SCAN_B - 1];
}

__global__ __launch_bounds__(128) void scan2_kernel(int* __restrict__ bsum)
{
    __shared__ int s[128];
    int t = threadIdx.x;
    int v = (t < SCAN_NB) ? bsum[t] : 0;
    s[t] = v;
    __syncthreads();
    #pragma unroll
    for (int d = 1; d < 128; d <<= 1) {
        int u = (t >= d) ? s[t - d] : 0;
        __syncthreads();
        s[t] += u;
        __syncthreads();
    }
    if (t < SCAN_NB) bsum[t] = s[t] - v;                // exclusive
}

__global__ __launch_bounds__(SCAN_B) void scan3_kernel(
    int* __restrict__ off, const int* __restrict__ bsum, int* __restrict__ cur)
{
    int i = blockIdx.x * SCAN_B + threadIdx.x;
    if (i < N_NODES) {
        int o = off[i] + bsum[blockIdx.x];
        off[i] = o;
        cur[i] = o;
    }
    if (i == 0) off[N_NODES] = N_EDGES;                 // sentinel
}

__global__ __launch_bounds__(256) void bucket_kernel(
    const int* __restrict__ rows, const int* __restrict__ cols,
    const float* __restrict__ vals, int* __restrict__ cur,
    int* __restrict__ scol, float* __restrict__ sval)
{
    int e = blockIdx.x * blockDim.x + threadIdx.x;
    if (e < N_EDGES) {
        int p = atomicAdd(&cur[rows[e]], 1);
        scol[p] = cols[e];
        sval[p] = vals[e];
    }
}

// ---------------------------------------------------------------------------
// Aggregate: one warp per node; register accumulation over its CSR segment;
// fused ELU epilogue. No atomics, no output memset needed.
// ---------------------------------------------------------------------------
__global__ __launch_bounds__(256) void aggregate_kernel(
    const float* __restrict__ H, const int* __restrict__ off,
    const int* __restrict__ scol, const float* __restrict__ sval,
    float* __restrict__ out)
{
    int w = (blockIdx.x * blockDim.x + threadIdx.x) >> 5;
    int lane = threadIdx.x & 31;
    if (w >= N_NODES) return;

    int beg = off[w];
    int end = off[w + 1];

    float4 acc = make_float4(0.f, 0.f, 0.f, 0.f);
    #pragma unroll 4
    for (int j = beg; j < end; j++) {
        int   c = scol[j];             // warp-uniform broadcast load
        float v = sval[j];
        float4 hv = ((const float4*)H)[c * 32 + lane];
        acc.x += v * hv.x;
        acc.y += v * hv.y;
        acc.z += v * hv.z;
        acc.w += v * hv.w;
    }
    acc.x = acc.x > 0.f ? acc.x : expm1f(acc.x);
    acc.y = acc.y > 0.f ? acc.y : expm1f(acc.y);
    acc.z = acc.z > 0.f ? acc.z : expm1f(acc.z);
    acc.w = acc.w > 0.f ? acc.w : expm1f(acc.w);
    ((float4*)out)[w * 32 + lane] = acc;
}

extern "C" void kernel_launch(void* const* d_in, const int* in_sizes, int n_in,
                              void* d_out, int out_size)
{
    const float* x    = (const float*)d_in[0];   // [50000,128]
    const float* W    = (const float*)d_in[1];   // [2,128,128]
    const float* b    = (const float*)d_in[2];   // [2,128]
    const int*   rows = (const int*)d_in[3];     // [2,800000]
    const int*   cols = (const int*)d_in[4];     // [2,800000]
    const float* vals = (const float*)d_in[5];   // [2,800000]
    float* out = (float*)d_out;                  // [50000,128]

    float *h_ptr, *x_ptr;
    int *cnt_b, *off_b, *cur_b, *bsum_b, *scol_b;
    float *sval_b;
    cudaGetSymbolAddress((void**)&h_ptr,  g_h);
    cudaGetSymbolAddress((void**)&x_ptr,  g_x);
    cudaGetSymbolAddress((void**)&cnt_b,  g_cnt);
    cudaGetSymbolAddress((void**)&off_b,  g_off);
    cudaGetSymbolAddress((void**)&cur_b,  g_cur);
    cudaGetSymbolAddress((void**)&bsum_b, g_bsum);
    cudaGetSymbolAddress((void**)&scol_b, g_scol);
    cudaGetSymbolAddress((void**)&sval_b, g_sval);

    const int gemm_smem = (64 * 128 + 128 * 128) * sizeof(float);  // 96 KB
    cudaFuncSetAttribute(gemm_kernel,
                         cudaFuncAttributeMaxDynamicSharedMemorySize, gemm_smem);

    const int gemm_grid = (N_NODES + 63) / 64;
    const int edge_grid = (N_EDGES + 255) / 256;
    const int agg_grid  = (N_NODES * 32 + 255) / 256;   // warp per node

    int*   cntL[2]  = {cnt_b,  cnt_b  + N_NODES};
    int*   offL[2]  = {off_b,  off_b  + (N_NODES + 1)};
    int*   curL[2]  = {cur_b,  cur_b  + N_NODES};
    int*   bsumL[2] = {bsum_b, bsum_b + 128};
    int*   scolL[2] = {scol_b, scol_b + N_EDGES};
    float* svalL[2] = {sval_b, sval_b + N_EDGES};

    // ---- CSR builds for both layers (depend only on edge inputs) ----
    if (s_async_ok) {
        cudaEventRecord(ev_fork, 0);
        for (int l = 0; l < 2; l++) {
            cudaStream_t s = s_csr[l];
            const int* rl = rows + (size_t)l * N_EDGES;
            cudaStreamWaitEvent(s, ev_fork, 0);
            cudaMemsetAsync(cntL[l], 0, N_NODES * sizeof(int), s);
            hist_kernel <<<edge_grid, 256, 0, s>>>(rl, cntL[l]);
            scan1_kernel<<<SCAN_NB, SCAN_B, 0, s>>>(cntL[l], offL[l], bsumL[l]);
            scan2_kernel<<<1, 128, 0, s>>>(bsumL[l]);
            scan3_kernel<<<SCAN_NB, SCAN_B, 0, s>>>(offL[l], bsumL[l], curL[l]);
            bucket_kernel<<<edge_grid, 256, 0, s>>>(
                rl, cols + (size_t)l * N_EDGES, vals + (size_t)l * N_EDGES,
                curL[l], scolL[l], svalL[l]);
            cudaEventRecord(ev_done[l], s);
        }
    } else {
        // Fallback: serial CSR builds on the main stream
        for (int l = 0; l < 2; l++) {
            const int* rl = rows + (size_t)l * N_EDGES;
            cudaMemsetAsync(cntL[l], 0, N_NODES * sizeof(int));
            hist_kernel <<<edge_grid, 256>>>(rl, cntL[l]);
            scan1_kernel<<<SCAN_NB, SCAN_B>>>(cntL[l], offL[l], bsumL[l]);
            scan2_kernel<<<1, 128>>>(bsumL[l]);
            scan3_kernel<<<SCAN_NB, SCAN_B>>>(offL[l], bsumL[l], curL[l]);
            bucket_kernel<<<edge_grid, 256>>>(
                rl, cols + (size_t)l * N_EDGES, vals + (size_t)l * N_EDGES,
                curL[l], scolL[l], svalL[l]);
        }
    }

    // ---- Layer 0 ----
    gemm_kernel<<<gemm_grid, 256, gemm_smem>>>(x, W, b, h_ptr);
    if (s_async_ok) cudaStreamWaitEvent(0, ev_done[0], 0);
    aggregate_kernel<<<agg_grid, 256>>>(h_ptr, offL[0], scolL[0], svalL[0], x_ptr);

    // ---- Layer 1 ----
    gemm_kernel<<<gemm_grid, 256, gemm_smem>>>(x_ptr, W + 128 * 128, b + 128, h_ptr);
    if (s_async_ok) cudaStreamWaitEvent(0, ev_done[1], 0);
    aggregate_kernel<<<agg_grid, 256>>>(h_ptr, offL[1], scolL[1], svalL[1], out);
}

// round 6
// speedup vs baseline: 1.6456x; 1.0005x over previous
#include <cuda_runtime.h>
#include <math.h>

#define N_NODES 50000
#define N_FEAT  128
#define N_EDGES 800000

#define SCAN_B   512
#define SCAN_NB  ((N_NODES + SCAN_B - 1) / SCAN_B)   // 98

// ---- Scratch (allocation-free rule: __device__ globals); per-layer CSR sets ----
__device__ float g_h[N_NODES * N_FEAT];       // per-layer linear output
__device__ float g_x[N_NODES * N_FEAT];       // layer-0 activation
__device__ int   g_cnt [2][N_NODES];
__device__ int   g_off [2][N_NODES + 1];      // +1: sentinel end = N_EDGES
__device__ int   g_cur [2][N_NODES];
__device__ int   g_bsum[2][128];
__device__ int   g_scol[2][N_EDGES];
__device__ float g_sval[2][N_EDGES];

// ---- Streams/events for capture-time fork/join (created once, no device mem APIs)
static cudaStream_t s_csr[2];
static cudaEvent_t  ev_fork, ev_done[2];
static bool s_async_ok = false;
struct AsyncInit {
    AsyncInit() {
        bool ok = true;
        ok &= cudaStreamCreateWithFlags(&s_csr[0], cudaStreamNonBlocking) == cudaSuccess;
        ok &= cudaStreamCreateWithFlags(&s_csr[1], cudaStreamNonBlocking) == cudaSuccess;
        ok &= cudaEventCreateWithFlags(&ev_fork,    cudaEventDisableTiming) == cudaSuccess;
        ok &= cudaEventCreateWithFlags(&ev_done[0], cudaEventDisableTiming) == cudaSuccess;
        ok &= cudaEventCreateWithFlags(&ev_done[1], cudaEventDisableTiming) == cudaSuccess;
        s_async_ok = ok;
    }
};
static AsyncInit s_async_init;

// ---------------------------------------------------------------------------
// GEMM: H[n][j] = sum_k X[n][k] * W[k][j] + B[j]
// 64x128 tile, full K in smem (96 KB). k stepped by 4 with float4 As loads.
// ---------------------------------------------------------------------------
__global__ __launch_bounds__(256) void gemm_kernel(
    const float* __restrict__ X, const float* __restrict__ W,
    const float* __restrict__ B, float* __restrict__ H)
{
    extern __shared__ float smem[];
    float* As = smem;               // [64][128]
    float* Ws = smem + 64 * 128;    // [128][128]
    float4* As4 = (float4*)As;

    const int tid = threadIdx.x;
    const int rowBase = blockIdx.x * 64;

    const float4* W4 = (const float4*)W;
    float4* Ws4 = (float4*)Ws;
    #pragma unroll
    for (int i = tid; i < 128 * 32; i += 256) Ws4[i] = W4[i];

    #pragma unroll
    for (int i = tid; i < 64 * 32; i += 256) {
        int r = i >> 5, c4 = i & 31;
        int gr = rowBase + r;
        float4 v = make_float4(0.f, 0.f, 0.f, 0.f);
        if (gr < N_NODES) v = ((const float4*)X)[gr * 32 + c4];
        As4[i] = v;
    }
    __syncthreads();

    const int warp = tid >> 5, lane = tid & 31;
    const int r0 = warp * 8;
    const int c0 = lane * 4;

    float acc[8][4];
    #pragma unroll
    for (int i = 0; i < 8; i++)
        #pragma unroll
        for (int j = 0; j < 4; j++) acc[i][j] = 0.f;

    #pragma unroll 2
    for (int k4 = 0; k4 < 32; k4++) {
        float4 a[8];
        #pragma unroll
        for (int i = 0; i < 8; i++) a[i] = As4[(r0 + i) * 32 + k4];  // broadcast

        #pragma unroll
        for (int kk = 0; kk < 4; kk++) {
            float4 w = *(const float4*)&Ws[(k4 * 4 + kk) * 128 + c0];
            #pragma unroll
            for (int i = 0; i < 8; i++) {
                float av = (kk == 0) ? a[i].x : (kk == 1) ? a[i].y
                         : (kk == 2) ? a[i].z : a[i].w;
                acc[i][0] += av * w.x;
                acc[i][1] += av * w.y;
                acc[i][2] += av * w.z;
                acc[i][3] += av * w.w;
            }
        }
    }

    float4 bb = *(const float4*)&B[c0];
    #pragma unroll
    for (int i = 0; i < 8; i++) {
        int gr = rowBase + r0 + i;
        if (gr < N_NODES) {
            float4 o = make_float4(acc[i][0] + bb.x, acc[i][1] + bb.y,
                                   acc[i][2] + bb.z, acc[i][3] + bb.w);
            ((float4*)H)[gr * 32 + (c0 >> 2)] = o;
        }
    }
}

// ---------------------------------------------------------------------------
// CSR build: histogram -> 3-kernel exclusive scan -> bucket (counting sort)
// ---------------------------------------------------------------------------
__global__ __launch_bounds__(256) void hist_kernel(
    const int* __restrict__ rows, int* __restrict__ cnt)
{
    int e = blockIdx.x * blockDim.x + threadIdx.x;
    if (e < N_EDGES) atomicAdd(&cnt[rows[e]], 1);
}

__global__ __launch_bounds__(SCAN_B) void scan1_kernel(
    const int* __restrict__ cnt, int* __restrict__ off, int* __restrict__ bsum)
{
    __shared__ int s[SCAN_B];
    int i = blockIdx.x * SCAN_B + threadIdx.x;
    int v = (i < N_NODES) ? cnt[i] : 0;
    s[threadIdx.x] = v;
    __syncthreads();
    #pragma unroll
    for (int d = 1; d < SCAN_B; d <<= 1) {
        int t = (threadIdx.x >= d) ? s[threadIdx.x - d] : 0;
        __syncthreads();
        s[threadIdx.x] += t;
        __syncthreads();
    }
    if (i < N_NODES) off[i] = s[threadIdx.x] - v;       // exclusive in-block
    if (threadIdx.x == SCAN_B - 1) bsum[blockIdx.x] = s[SCAN_B - 1];
}

__global__ __launch_bounds__(128) void scan2_kernel(int* __restrict__ bsum)
{
    __shared__ int s[128];
    int t = threadIdx.x;
    int v = (t < SCAN_NB) ? bsum[t] : 0;
    s[t] = v;
    __syncthreads();
    #pragma unroll
    for (int d = 1; d < 128; d <<= 1) {
        int u = (t >= d) ? s[t - d] : 0;
        __syncthreads();
        s[t] += u;
        __syncthreads();
    }
    if (t < SCAN_NB) bsum[t] = s[t] - v;                // exclusive
}

__global__ __launch_bounds__(SCAN_B) void scan3_kernel(
    int* __restrict__ off, const int* __restrict__ bsum, int* __restrict__ cur)
{
    int i = blockIdx.x * SCAN_B + threadIdx.x;
    if (i < N_NODES) {
        int o = off[i] + bsum[blockIdx.x];
        off[i] = o;
        cur[i] = o;
    }
    if (i == 0) off[N_NODES] = N_EDGES;                 // sentinel
}

__global__ __launch_bounds__(256) void bucket_kernel(
    const int* __restrict__ rows, const int* __restrict__ cols,
    const float* __restrict__ vals, int* __restrict__ cur,
    int* __restrict__ scol, float* __restrict__ sval)
{
    int e = blockIdx.x * blockDim.x + threadIdx.x;
    if (e < N_EDGES) {
        int p = atomicAdd(&cur[rows[e]], 1);
        scol[p] = cols[e];
        sval[p] = vals[e];
    }
}

// ---------------------------------------------------------------------------
// Aggregate: one warp per node; register accumulation over its CSR segment;
// fused ELU epilogue. No atomics, no output memset needed.
// ---------------------------------------------------------------------------
__global__ __launch_bounds__(256) void aggregate_kernel(
    const float* __restrict__ H, const int* __restrict__ off,
    const int* __restrict__ scol, const float* __restrict__ sval,
    float* __restrict__ out)
{
    int w = (blockIdx.x * blockDim.x + threadIdx.x) >> 5;
    int lane = threadIdx.x & 31;
    if (w >= N_NODES) return;

    int beg = off[w];
    int end = off[w + 1];

    float4 acc = make_float4(0.f, 0.f, 0.f, 0.f);
    #pragma unroll 4
    for (int j = beg; j < end; j++) {
        int   c = scol[j];             // warp-uniform broadcast load
        float v = sval[j];
        float4 hv = ((const float4*)H)[c * 32 + lane];
        acc.x += v * hv.x;
        acc.y += v * hv.y;
        acc.z += v * hv.z;
        acc.w += v * hv.w;
    }
    acc.x = acc.x > 0.f ? acc.x : expm1f(acc.x);
    acc.y = acc.y > 0.f ? acc.y : expm1f(acc.y);
    acc.z = acc.z > 0.f ? acc.z : expm1f(acc.z);
    acc.w = acc.w > 0.f ? acc.w : expm1f(acc.w);
    ((float4*)out)[w * 32 + lane] = acc;
}

extern "C" void kernel_launch(void* const* d_in, const int* in_sizes, int n_in,
                              void* d_out, int out_size)
{
    const float* x    = (const float*)d_in[0];   // [50000,128]
    const float* W    = (const float*)d_in[1];   // [2,128,128]
    const float* b    = (const float*)d_in[2];   // [2,128]
    const int*   rows = (const int*)d_in[3];     // [2,800000]
    const int*   cols = (const int*)d_in[4];     // [2,800000]
    const float* vals = (const float*)d_in[5];   // [2,800000]
    float* out = (float*)d_out;                  // [50000,128]

    float *h_ptr, *x_ptr;
    int *cnt_b, *off_b, *cur_b, *bsum_b, *scol_b;
    float *sval_b;
    cudaGetSymbolAddress((void**)&h_ptr,  g_h);
    cudaGetSymbolAddress((void**)&x_ptr,  g_x);
    cudaGetSymbolAddress((void**)&cnt_b,  g_cnt);
    cudaGetSymbolAddress((void**)&off_b,  g_off);
    cudaGetSymbolAddress((void**)&cur_b,  g_cur);
    cudaGetSymbolAddress((void**)&bsum_b, g_bsum);
    cudaGetSymbolAddress((void**)&scol_b, g_scol);
    cudaGetSymbolAddress((void**)&sval_b, g_sval);

    const int gemm_smem = (64 * 128 + 128 * 128) * sizeof(float);  // 96 KB
    cudaFuncSetAttribute(gemm_kernel,
                         cudaFuncAttributeMaxDynamicSharedMemorySize, gemm_smem);

    const int gemm_grid = (N_NODES + 63) / 64;
    const int edge_grid = (N_EDGES + 255) / 256;
    const int agg_grid  = (N_NODES * 32 + 255) / 256;   // warp per node

    int*   cntL[2]  = {cnt_b,  cnt_b  + N_NODES};
    int*   offL[2]  = {off_b,  off_b  + (N_NODES + 1)};
    int*   curL[2]  = {cur_b,  cur_b  + N_NODES};
    int*   bsumL[2] = {bsum_b, bsum_b + 128};
    int*   scolL[2] = {scol_b, scol_b + N_EDGES};
    float* svalL[2] = {sval_b, sval_b + N_EDGES};

    // ---- CSR builds for both layers (depend only on edge inputs) ----
    if (s_async_ok) {
        cudaEventRecord(ev_fork, 0);
        for (int l = 0; l < 2; l++) {
            cudaStream_t s = s_csr[l];
            const int* rl = rows + (size_t)l * N_EDGES;
            cudaStreamWaitEvent(s, ev_fork, 0);
            cudaMemsetAsync(cntL[l], 0, N_NODES * sizeof(int), s);
            hist_kernel <<<edge_grid, 256, 0, s>>>(rl, cntL[l]);
            scan1_kernel<<<SCAN_NB, SCAN_B, 0, s>>>(cntL[l], offL[l], bsumL[l]);
            scan2_kernel<<<1, 128, 0, s>>>(bsumL[l]);
            scan3_kernel<<<SCAN_NB, SCAN_B, 0, s>>>(offL[l], bsumL[l], curL[l]);
            bucket_kernel<<<edge_grid, 256, 0, s>>>(
                rl, cols + (size_t)l * N_EDGES, vals + (size_t)l * N_EDGES,
                curL[l], scolL[l], svalL[l]);
            cudaEventRecord(ev_done[l], s);
        }
    } else {
        // Fallback: serial CSR builds on the main stream
        for (int l = 0; l < 2; l++) {
            const int* rl = rows + (size_t)l * N_EDGES;
            cudaMemsetAsync(cntL[l], 0, N_NODES * sizeof(int));
            hist_kernel <<<edge_grid, 256>>>(rl, cntL[l]);
            scan1_kernel<<<SCAN_NB, SCAN_B>>>(cntL[l], offL[l], bsumL[l]);
            scan2_kernel<<<1, 128>>>(bsumL[l]);
            scan3_kernel<<<SCAN_NB, SCAN_B>>>(offL[l], bsumL[l], curL[l]);
            bucket_kernel<<<edge_grid, 256>>>(
                rl, cols + (size_t)l * N_EDGES, vals + (size_t)l * N_EDGES,
                curL[l], scolL[l], svalL[l]);
        }
    }

    // ---- Layer 0 ----
    gemm_kernel<<<gemm_grid, 256, gemm_smem>>>(x, W, b, h_ptr);
    if (s_async_ok) cudaStreamWaitEvent(0, ev_done[0], 0);
    aggregate_kernel<<<agg_grid, 256>>>(h_ptr, offL[0], scolL[0], svalL[0], x_ptr);

    // ---- Layer 1 ----
    gemm_kernel<<<gemm_grid, 256, gemm_smem>>>(x_ptr, W + 128 * 128, b + 128, h_ptr);
    if (s_async_ok) cudaStreamWaitEvent(0, ev_done[1], 0);
    aggregate_kernel<<<agg_grid, 256>>>(h_ptr, offL[1], scolL[1], svalL[1], out);
}

// round 7
// speedup vs baseline: 1.7032x; 1.0350x over previous
#include <cuda_runtime.h>
#include <cuda_fp16.h>
#include <math.h>

#define N_NODES 50000
#define N_FEAT  128
#define N_EDGES 800000

#define SCAN_B   512
#define SCAN_NB  ((N_NODES + SCAN_B - 1) / SCAN_B)   // 98

// ---- Scratch (allocation-free rule: __device__ globals) ----
__device__ uint2 g_h2[N_NODES * 32];          // H in half2 pairs: 128 half/row = 32 uint2
__device__ float g_x[N_NODES * N_FEAT];       // layer-0 activation
__device__ int   g_cnt [2][N_NODES];
__device__ int   g_off [2][N_NODES + 1];      // +1: sentinel end = N_EDGES
__device__ int   g_cur [2][N_NODES];
__device__ int   g_bsum[2][128];
__device__ int   g_scol[2][N_EDGES];
__device__ float g_sval[2][N_EDGES];

// ---- Streams/events for capture-time fork/join (created once) ----
static cudaStream_t s_csr[2];
static cudaEvent_t  ev_fork, ev_done[2];
static bool s_async_ok = false;
struct AsyncInit {
    AsyncInit() {
        bool ok = true;
        ok &= cudaStreamCreateWithFlags(&s_csr[0], cudaStreamNonBlocking) == cudaSuccess;
        ok &= cudaStreamCreateWithFlags(&s_csr[1], cudaStreamNonBlocking) == cudaSuccess;
        ok &= cudaEventCreateWithFlags(&ev_fork,    cudaEventDisableTiming) == cudaSuccess;
        ok &= cudaEventCreateWithFlags(&ev_done[0], cudaEventDisableTiming) == cudaSuccess;
        ok &= cudaEventCreateWithFlags(&ev_done[1], cudaEventDisableTiming) == cudaSuccess;
        s_async_ok = ok;
    }
};
static AsyncInit s_async_init;

// ---------------------------------------------------------------------------
// GEMM: H[n][j] = sum_k X[n][k] * W[k][j] + B[j], output stored as half2.
// 64x128 tile, full K in smem (96 KB). fp32 accumulate; fp16 only on store.
// ---------------------------------------------------------------------------
__global__ __launch_bounds__(256) void gemm_kernel(
    const float* __restrict__ X, const float* __restrict__ W,
    const float* __restrict__ B, uint2* __restrict__ H2)
{
    extern __shared__ float smem[];
    float* As = smem;               // [64][128]
    float* Ws = smem + 64 * 128;    // [128][128]
    float4* As4 = (float4*)As;

    const int tid = threadIdx.x;
    const int rowBase = blockIdx.x * 64;

    const float4* W4 = (const float4*)W;
    float4* Ws4 = (float4*)Ws;
    #pragma unroll
    for (int i = tid; i < 128 * 32; i += 256) Ws4[i] = W4[i];

    #pragma unroll
    for (int i = tid; i < 64 * 32; i += 256) {
        int r = i >> 5, c4 = i & 31;
        int gr = rowBase + r;
        float4 v = make_float4(0.f, 0.f, 0.f, 0.f);
        if (gr < N_NODES) v = ((const float4*)X)[gr * 32 + c4];
        As4[i] = v;
    }
    __syncthreads();

    const int warp = tid >> 5, lane = tid & 31;
    const int r0 = warp * 8;
    const int c0 = lane * 4;

    float acc[8][4];
    #pragma unroll
    for (int i = 0; i < 8; i++)
        #pragma unroll
        for (int j = 0; j < 4; j++) acc[i][j] = 0.f;

    #pragma unroll 2
    for (int k4 = 0; k4 < 32; k4++) {
        float4 a[8];
        #pragma unroll
        for (int i = 0; i < 8; i++) a[i] = As4[(r0 + i) * 32 + k4];  // broadcast

        #pragma unroll
        for (int kk = 0; kk < 4; kk++) {
            float4 w = *(const float4*)&Ws[(k4 * 4 + kk) * 128 + c0];
            #pragma unroll
            for (int i = 0; i < 8; i++) {
                float av = (kk == 0) ? a[i].x : (kk == 1) ? a[i].y
                         : (kk == 2) ? a[i].z : a[i].w;
                acc[i][0] += av * w.x;
                acc[i][1] += av * w.y;
                acc[i][2] += av * w.z;
                acc[i][3] += av * w.w;
            }
        }
    }

    float4 bb = *(const float4*)&B[c0];
    #pragma unroll
    for (int i = 0; i < 8; i++) {
        int gr = rowBase + r0 + i;
        if (gr < N_NODES) {
            __half2 h0 = __floats2half2_rn(acc[i][0] + bb.x, acc[i][1] + bb.y);
            __half2 h1 = __floats2half2_rn(acc[i][2] + bb.z, acc[i][3] + bb.w);
            uint2 u;
            u.x = *reinterpret_cast<unsigned*>(&h0);
            u.y = *reinterpret_cast<unsigned*>(&h1);
            H2[gr * 32 + (c0 >> 2)] = u;
        }
    }
}

// ---------------------------------------------------------------------------
// CSR build: histogram -> 3-kernel exclusive scan -> bucket (counting sort)
// ---------------------------------------------------------------------------
__global__ __launch_bounds__(256) void hist_kernel(
    const int* __restrict__ rows, int* __restrict__ cnt)
{
    int e = blockIdx.x * blockDim.x + threadIdx.x;
    if (e < N_EDGES) atomicAdd(&cnt[rows[e]], 1);
}

__global__ __launch_bounds__(SCAN_B) void scan1_kernel(
    const int* __restrict__ cnt, int* __restrict__ off, int* __restrict__ bsum)
{
    __shared__ int s[SCAN_B];
    int i = blockIdx.x * SCAN_B + threadIdx.x;
    int v = (i < N_NODES) ? cnt[i] : 0;
    s[threadIdx.x] = v;
    __syncthreads();
    #pragma unroll
    for (int d = 1; d < SCAN_B; d <<= 1) {
        int t = (threadIdx.x >= d) ? s[threadIdx.x - d] : 0;
        __syncthreads();
        s[threadIdx.x] += t;
        __syncthreads();
    }
    if (i < N_NODES) off[i] = s[threadIdx.x] - v;       // exclusive in-block
    if (threadIdx.x == SCAN_B - 1) bsum[blockIdx.x] = s[SCAN_B - 1];
}

__global__ __launch_bounds__(128) void scan2_kernel(int* __restrict__ bsum)
{
    __shared__ int s[128];
    int t = threadIdx.x;
    int v = (t < SCAN_NB) ? bsum[t] : 0;
    s[t] = v;
    __syncthreads();
    #pragma unroll
    for (int d = 1; d < 128; d <<= 1) {
        int u = (t >= d) ? s[t - d] : 0;
        __syncthreads();
        s[t] += u;
        __syncthreads();
    }
    if (t < SCAN_NB) bsum[t] = s[t] - v;                // exclusive
}

__global__ __launch_bounds__(SCAN_B) void scan3_kernel(
    int* __restrict__ off, const int* __restrict__ bsum, int* __restrict__ cur)
{
    int i = blockIdx.x * SCAN_B + threadIdx.x;
    if (i < N_NODES) {
        int o = off[i] + bsum[blockIdx.x];
        off[i] = o;
        cur[i] = o;
    }
    if (i == 0) off[N_NODES] = N_EDGES;                 // sentinel
}

__global__ __launch_bounds__(256) void bucket_kernel(
    const int* __restrict__ rows, const int* __restrict__ cols,
    const float* __restrict__ vals, int* __restrict__ cur,
    int* __restrict__ scol, float* __restrict__ sval)
{
    int e = blockIdx.x * blockDim.x + threadIdx.x;
    if (e < N_EDGES) {
        int p = atomicAdd(&cur[rows[e]], 1);
        scol[p] = cols[e];
        sval[p] = vals[e];
    }
}

// ---------------------------------------------------------------------------
// Aggregate: one warp per node; gathers half2 H rows (8B/lane), accumulates
// fp32, fused ELU. No atomics, no output memset.
// ---------------------------------------------------------------------------
__global__ __launch_bounds__(256) void aggregate_kernel(
    const uint2* __restrict__ H2, const int* __restrict__ off,
    const int* __restrict__ scol, const float* __restrict__ sval,
    float* __restrict__ out)
{
    int w = (blockIdx.x * blockDim.x + threadIdx.x) >> 5;
    int lane = threadIdx.x & 31;
    if (w >= N_NODES) return;

    int beg = off[w];
    int end = off[w + 1];

    float4 acc = make_float4(0.f, 0.f, 0.f, 0.f);
    #pragma unroll 4
    for (int j = beg; j < end; j++) {
        int   c = scol[j];             // warp-uniform broadcast load
        float v = sval[j];
        uint2 u = H2[c * 32 + lane];
        __half2 p0 = *reinterpret_cast<__half2*>(&u.x);
        __half2 p1 = *reinterpret_cast<__half2*>(&u.y);
        float2 f0 = __half22float2(p0);
        float2 f1 = __half22float2(p1);
        acc.x += v * f0.x;
        acc.y += v * f0.y;
        acc.z += v * f1.x;
        acc.w += v * f1.y;
    }
    acc.x = acc.x > 0.f ? acc.x : expm1f(acc.x);
    acc.y = acc.y > 0.f ? acc.y : expm1f(acc.y);
    acc.z = acc.z > 0.f ? acc.z : expm1f(acc.z);
    acc.w = acc.w > 0.f ? acc.w : expm1f(acc.w);
    ((float4*)out)[w * 32 + lane] = acc;
}

extern "C" void kernel_launch(void* const* d_in, const int* in_sizes, int n_in,
                              void* d_out, int out_size)
{
    const float* x    = (const float*)d_in[0];   // [50000,128]
    const float* W    = (const float*)d_in[1];   // [2,128,128]
    const float* b    = (const float*)d_in[2];   // [2,128]
    const int*   rows = (const int*)d_in[3];     // [2,800000]
    const int*   cols = (const int*)d_in[4];     // [2,800000]
    const float* vals = (const float*)d_in[5];   // [2,800000]
    float* out = (float*)d_out;                  // [50000,128]

    uint2* h2_ptr;
    float* x_ptr;
    int *cnt_b, *off_b, *cur_b, *bsum_b, *scol_b;
    float *sval_b;
    cudaGetSymbolAddress((void**)&h2_ptr, g_h2);
    cudaGetSymbolAddress((void**)&x_ptr,  g_x);
    cudaGetSymbolAddress((void**)&cnt_b,  g_cnt);
    cudaGetSymbolAddress((void**)&off_b,  g_off);
    cudaGetSymbolAddress((void**)&cur_b,  g_cur);
    cudaGetSymbolAddress((void**)&bsum_b, g_bsum);
    cudaGetSymbolAddress((void**)&scol_b, g_scol);
    cudaGetSymbolAddress((void**)&sval_b, g_sval);

    const int gemm_smem = (64 * 128 + 128 * 128) * sizeof(float);  // 96 KB
    cudaFuncSetAttribute(gemm_kernel,
                         cudaFuncAttributeMaxDynamicSharedMemorySize, gemm_smem);

    const int gemm_grid = (N_NODES + 63) / 64;
    const int edge_grid = (N_EDGES + 255) / 256;
    const int agg_grid  = (N_NODES * 32 + 255) / 256;   // warp per node

    int*   cntL[2]  = {cnt_b,  cnt_b  + N_NODES};
    int*   offL[2]  = {off_b,  off_b  + (N_NODES + 1)};
    int*   curL[2]  = {cur_b,  cur_b  + N_NODES};
    int*   bsumL[2] = {bsum_b, bsum_b + 128};
    int*   scolL[2] = {scol_b, scol_b + N_EDGES};
    float* svalL[2] = {sval_b, sval_b + N_EDGES};

    // ---- CSR builds for both layers (depend only on edge inputs) ----
    if (s_async_ok) {
        cudaEventRecord(ev_fork, 0);
        for (int l = 0; l < 2; l++) {
            cudaStream_t s = s_csr[l];
            const int* rl = rows + (size_t)l * N_EDGES;
            cudaStreamWaitEvent(s, ev_fork, 0);
            cudaMemsetAsync(cntL[l], 0, N_NODES * sizeof(int), s);
            hist_kernel <<<edge_grid, 256, 0, s>>>(rl, cntL[l]);
            scan1_kernel<<<SCAN_NB, SCAN_B, 0, s>>>(cntL[l], offL[l], bsumL[l]);
            scan2_kernel<<<1, 128, 0, s>>>(bsumL[l]);
            scan3_kernel<<<SCAN_NB, SCAN_B, 0, s>>>(offL[l], bsumL[l], curL[l]);
            bucket_kernel<<<edge_grid, 256, 0, s>>>(
                rl, cols + (size_t)l * N_EDGES, vals + (size_t)l * N_EDGES,
                curL[l], scolL[l], svalL[l]);
            cudaEventRecord(ev_done[l], s);
        }
    } else {
        for (int l = 0; l < 2; l++) {
            const int* rl = rows + (size_t)l * N_EDGES;
            cudaMemsetAsync(cntL[l], 0, N_NODES * sizeof(int));
            hist_kernel <<<edge_grid, 256>>>(rl, cntL[l]);
            scan1_kernel<<<SCAN_NB, SCAN_B>>>(cntL[l], offL[l], bsumL[l]);
            scan2_kernel<<<1, 128>>>(bsumL[l]);
            scan3_kernel<<<SCAN_NB, SCAN_B>>>(offL[l], bsumL[l], curL[l]);
            bucket_kernel<<<edge_grid, 256>>>(
                rl, cols + (size_t)l * N_EDGES, vals + (size_t)l * N_EDGES,
                curL[l], scolL[l], svalL[l]);
        }
    }

    // ---- Layer 0 ----
    gemm_kernel<<<gemm_grid, 256, gemm_smem>>>(x, W, b, h2_ptr);
    if (s_async_ok) cudaStreamWaitEvent(0, ev_done[0], 0);
    aggregate_kernel<<<agg_grid, 256>>>(h2_ptr, offL[0], scolL[0], svalL[0], x_ptr);

    // ---- Layer 1 ----
    gemm_kernel<<<gemm_grid, 256, gemm_smem>>>(x_ptr, W + 128 * 128, b + 128, h2_ptr);
    if (s_async_ok) cudaStreamWaitEvent(0, ev_done[1], 0);
    aggregate_kernel<<<agg_grid, 256>>>(h2_ptr, offL[1], scolL[1], svalL[1], out);
}

// round 8
// speedup vs baseline: 1.7043x; 1.0007x over previous
#include <cuda_runtime.h>
#include <cuda_fp16.h>
#include <math.h>

#define N_NODES 50000
#define N_FEAT  128
#define N_EDGES 800000

#define SCAN_B   512
#define SCAN_NB  ((N_NODES + SCAN_B - 1) / SCAN_B)   // 98

// ---- Scratch (allocation-free rule: __device__ globals) ----
__device__ uint2 g_h2[N_NODES * 32];          // H in half2 pairs: 128 half/row = 32 uint2
__device__ float g_x[N_NODES * N_FEAT];       // layer-0 activation
__device__ int   g_cnt [2][N_NODES];
__device__ int   g_off [2][N_NODES + 1];      // +1: sentinel end = N_EDGES
__device__ int   g_cur [2][N_NODES];
__device__ int   g_bsum[2][128];
__device__ int   g_scol[2][N_EDGES];
__device__ float g_sval[2][N_EDGES];

// ---- Streams/events for capture-time fork/join (created once) ----
static cudaStream_t s_csr[2];
static cudaEvent_t  ev_fork, ev_done[2];
static bool s_async_ok = false;
struct AsyncInit {
    AsyncInit() {
        bool ok = true;
        ok &= cudaStreamCreateWithFlags(&s_csr[0], cudaStreamNonBlocking) == cudaSuccess;
        ok &= cudaStreamCreateWithFlags(&s_csr[1], cudaStreamNonBlocking) == cudaSuccess;
        ok &= cudaEventCreateWithFlags(&ev_fork,    cudaEventDisableTiming) == cudaSuccess;
        ok &= cudaEventCreateWithFlags(&ev_done[0], cudaEventDisableTiming) == cudaSuccess;
        ok &= cudaEventCreateWithFlags(&ev_done[1], cudaEventDisableTiming) == cudaSuccess;
        s_async_ok = ok;
    }
};
static AsyncInit s_async_init;

// ---------------------------------------------------------------------------
// GEMM: H[n][j] = sum_k X[n][k] * W[k][j] + B[j], output stored as half2.
// 64x128 tile, full K in smem (96 KB). fp32 accumulate; fp16 only on store.
// ---------------------------------------------------------------------------
__global__ __launch_bounds__(256) void gemm_kernel(
    const float* __restrict__ X, const float* __restrict__ W,
    const float* __restrict__ B, uint2* __restrict__ H2)
{
    extern __shared__ float smem[];
    float* As = smem;               // [64][128]
    float* Ws = smem + 64 * 128;    // [128][128]
    float4* As4 = (float4*)As;

    const int tid = threadIdx.x;
    const int rowBase = blockIdx.x * 64;

    const float4* W4 = (const float4*)W;
    float4* Ws4 = (float4*)Ws;
    #pragma unroll
    for (int i = tid; i < 128 * 32; i += 256) Ws4[i] = W4[i];

    #pragma unroll
    for (int i = tid; i < 64 * 32; i += 256) {
        int r = i >> 5, c4 = i & 31;
        int gr = rowBase + r;
        float4 v = make_float4(0.f, 0.f, 0.f, 0.f);
        if (gr < N_NODES) v = ((const float4*)X)[gr * 32 + c4];
        As4[i] = v;
    }
    __syncthreads();

    const int warp = tid >> 5, lane = tid & 31;
    const int r0 = warp * 8;
    const int c0 = lane * 4;

    float acc[8][4];
    #pragma unroll
    for (int i = 0; i < 8; i++)
        #pragma unroll
        for (int j = 0; j < 4; j++) acc[i][j] = 0.f;

    #pragma unroll 2
    for (int k4 = 0; k4 < 32; k4++) {
        float4 a[8];
        #pragma unroll
        for (int i = 0; i < 8; i++) a[i] = As4[(r0 + i) * 32 + k4];  // broadcast

        #pragma unroll
        for (int kk = 0; kk < 4; kk++) {
            float4 w = *(const float4*)&Ws[(k4 * 4 + kk) * 128 + c0];
            #pragma unroll
            for (int i = 0; i < 8; i++) {
                float av = (kk == 0) ? a[i].x : (kk == 1) ? a[i].y
                         : (kk == 2) ? a[i].z : a[i].w;
                acc[i][0] += av * w.x;
                acc[i][1] += av * w.y;
                acc[i][2] += av * w.z;
                acc[i][3] += av * w.w;
            }
        }
    }

    float4 bb = *(const float4*)&B[c0];
    #pragma unroll
    for (int i = 0; i < 8; i++) {
        int gr = rowBase + r0 + i;
        if (gr < N_NODES) {
            __half2 h0 = __floats2half2_rn(acc[i][0] + bb.x, acc[i][1] + bb.y);
            __half2 h1 = __floats2half2_rn(acc[i][2] + bb.z, acc[i][3] + bb.w);
            uint2 u;
            u.x = *reinterpret_cast<unsigned*>(&h0);
            u.y = *reinterpret_cast<unsigned*>(&h1);
            H2[gr * 32 + (c0 >> 2)] = u;
        }
    }
}

// ---------------------------------------------------------------------------
// CSR build: histogram -> 3-kernel exclusive scan -> bucket (counting sort)
// ---------------------------------------------------------------------------
__global__ __launch_bounds__(256) void hist_kernel(
    const int* __restrict__ rows, int* __restrict__ cnt)
{
    int e = blockIdx.x * blockDim.x + threadIdx.x;
    if (e < N_EDGES) atomicAdd(&cnt[rows[e]], 1);
}

__global__ __launch_bounds__(SCAN_B) void scan1_kernel(
    const int* __restrict__ cnt, int* __restrict__ off, int* __restrict__ bsum)
{
    __shared__ int s[SCAN_B];
    int i = blockIdx.x * SCAN_B + threadIdx.x;
    int v = (i < N_NODES) ? cnt[i] : 0;
    s[threadIdx.x] = v;
    __syncthreads();
    #pragma unroll
    for (int d = 1; d < SCAN_B; d <<= 1) {
        int t = (threadIdx.x >= d) ? s[threadIdx.x - d] : 0;
        __syncthreads();
        s[threadIdx.x] += t;
        __syncthreads();
    }
    if (i < N_NODES) off[i] = s[threadIdx.x] - v;       // exclusive in-block
    if (threadIdx.x == SCAN_B - 1) bsum[blockIdx.x] = s[SCAN_B - 1];
}

__global__ __launch_bounds__(128) void scan2_kernel(int* __restrict__ bsum)
{
    __shared__ int s[128];
    int t = threadIdx.x;
    int v = (t < SCAN_NB) ? bsum[t] : 0;
    s[t] = v;
    __syncthreads();
    #pragma unroll
    for (int d = 1; d < 128; d <<= 1) {
        int u = (t >= d) ? s[t - d] : 0;
        __syncthreads();
        s[t] += u;
        __syncthreads();
    }
    if (t < SCAN_NB) bsum[t] = s[t] - v;                // exclusive
}

__global__ __launch_bounds__(SCAN_B) void scan3_kernel(
    int* __restrict__ off, const int* __restrict__ bsum, int* __restrict__ cur)
{
    int i = blockIdx.x * SCAN_B + threadIdx.x;
    if (i < N_NODES) {
        int o = off[i] + bsum[blockIdx.x];
        off[i] = o;
        cur[i] = o;
    }
    if (i == 0) off[N_NODES] = N_EDGES;                 // sentinel
}

__global__ __launch_bounds__(256) void bucket_kernel(
    const int* __restrict__ rows, const int* __restrict__ cols,
    const float* __restrict__ vals, int* __restrict__ cur,
    int* __restrict__ scol, float* __restrict__ sval)
{
    int e = blockIdx.x * blockDim.x + threadIdx.x;
    if (e < N_EDGES) {
        int p = atomicAdd(&cur[rows[e]], 1);
        scol[p] = cols[e];
        sval[p] = vals[e];
    }
}

// ---------------------------------------------------------------------------
// Aggregate: one warp per node; gathers half2 H rows (8B/lane), accumulates
// fp32, fused ELU. No atomics, no output memset.
// ---------------------------------------------------------------------------
__global__ __launch_bounds__(256) void aggregate_kernel(
    const uint2* __restrict__ H2, const int* __restrict__ off,
    const int* __restrict__ scol, const float* __restrict__ sval,
    float* __restrict__ out)
{
    int w = (blockIdx.x * blockDim.x + threadIdx.x) >> 5;
    int lane = threadIdx.x & 31;
    if (w >= N_NODES) return;

    int beg = off[w];
    int end = off[w + 1];

    float4 acc = make_float4(0.f, 0.f, 0.f, 0.f);
    #pragma unroll 4
    for (int j = beg; j < end; j++) {
        int   c = scol[j];             // warp-uniform broadcast load
        float v = sval[j];
        uint2 u = H2[c * 32 + lane];
        __half2 p0 = *reinterpret_cast<__half2*>(&u.x);
        __half2 p1 = *reinterpret_cast<__half2*>(&u.y);
        float2 f0 = __half22float2(p0);
        float2 f1 = __half22float2(p1);
        acc.x += v * f0.x;
        acc.y += v * f0.y;
        acc.z += v * f1.x;
        acc.w += v * f1.y;
    }
    acc.x = acc.x > 0.f ? acc.x : expm1f(acc.x);
    acc.y = acc.y > 0.f ? acc.y : expm1f(acc.y);
    acc.z = acc.z > 0.f ? acc.z : expm1f(acc.z);
    acc.w = acc.w > 0.f ? acc.w : expm1f(acc.w);
    ((float4*)out)[w * 32 + lane] = acc;
}

extern "C" void kernel_launch(void* const* d_in, const int* in_sizes, int n_in,
                              void* d_out, int out_size)
{
    const float* x    = (const float*)d_in[0];   // [50000,128]
    const float* W    = (const float*)d_in[1];   // [2,128,128]
    const float* b    = (const float*)d_in[2];   // [2,128]
    const int*   rows = (const int*)d_in[3];     // [2,800000]
    const int*   cols = (const int*)d_in[4];     // [2,800000]
    const float* vals = (const float*)d_in[5];   // [2,800000]
    float* out = (float*)d_out;                  // [50000,128]

    uint2* h2_ptr;
    float* x_ptr;
    int *cnt_b, *off_b, *cur_b, *bsum_b, *scol_b;
    float *sval_b;
    cudaGetSymbolAddress((void**)&h2_ptr, g_h2);
    cudaGetSymbolAddress((void**)&x_ptr,  g_x);
    cudaGetSymbolAddress((void**)&cnt_b,  g_cnt);
    cudaGetSymbolAddress((void**)&off_b,  g_off);
    cudaGetSymbolAddress((void**)&cur_b,  g_cur);
    cudaGetSymbolAddress((void**)&bsum_b, g_bsum);
    cudaGetSymbolAddress((void**)&scol_b, g_scol);
    cudaGetSymbolAddress((void**)&sval_b, g_sval);

    const int gemm_smem = (64 * 128 + 128 * 128) * sizeof(float);  // 96 KB
    cudaFuncSetAttribute(gemm_kernel,
                         cudaFuncAttributeMaxDynamicSharedMemorySize, gemm_smem);

    const int gemm_grid = (N_NODES + 63) / 64;
    const int edge_grid = (N_EDGES + 255) / 256;
    const int agg_grid  = (N_NODES * 32 + 255) / 256;   // warp per node

    int*   cntL[2]  = {cnt_b,  cnt_b  + N_NODES};
    int*   offL[2]  = {off_b,  off_b  + (N_NODES + 1)};
    int*   curL[2]  = {cur_b,  cur_b  + N_NODES};
    int*   bsumL[2] = {bsum_b, bsum_b + 128};
    int*   scolL[2] = {scol_b, scol_b + N_EDGES};
    float* svalL[2] = {sval_b, sval_b + N_EDGES};

    // ---- CSR builds for both layers (depend only on edge inputs) ----
    if (s_async_ok) {
        cudaEventRecord(ev_fork, 0);
        for (int l = 0; l < 2; l++) {
            cudaStream_t s = s_csr[l];
            const int* rl = rows + (size_t)l * N_EDGES;
            cudaStreamWaitEvent(s, ev_fork, 0);
            cudaMemsetAsync(cntL[l], 0, N_NODES * sizeof(int), s);
            hist_kernel <<<edge_grid, 256, 0, s>>>(rl, cntL[l]);
            scan1_kernel<<<SCAN_NB, SCAN_B, 0, s>>>(cntL[l], offL[l], bsumL[l]);
            scan2_kernel<<<1, 128, 0, s>>>(bsumL[l]);
            scan3_kernel<<<SCAN_NB, SCAN_B, 0, s>>>(offL[l], bsumL[l], curL[l]);
            bucket_kernel<<<edge_grid, 256, 0, s>>>(
                rl, cols + (size_t)l * N_EDGES, vals + (size_t)l * N_EDGES,
                curL[l], scolL[l], svalL[l]);
            cudaEventRecord(ev_done[l], s);
        }
    } else {
        for (int l = 0; l < 2; l++) {
            const int* rl = rows + (size_t)l * N_EDGES;
            cudaMemsetAsync(cntL[l], 0, N_NODES * sizeof(int));
            hist_kernel <<<edge_grid, 256>>>(rl, cntL[l]);
            scan1_kernel<<<SCAN_NB, SCAN_B>>>(cntL[l], offL[l], bsumL[l]);
            scan2_kernel<<<1, 128>>>(bsumL[l]);
            scan3_kernel<<<SCAN_NB, SCAN_B>>>(offL[l], bsumL[l], curL[l]);
            bucket_kernel<<<edge_grid, 256>>>(
                rl, cols + (size_t)l * N_EDGES, vals + (size_t)l * N_EDGES,
                curL[l], scolL[l], svalL[l]);
        }
    }

    // ---- Layer 0 ----
    gemm_kernel<<<gemm_grid, 256, gemm_smem>>>(x, W, b, h2_ptr);
    if (s_async_ok) cudaStreamWaitEvent(0, ev_done[0], 0);
    aggregate_kernel<<<agg_grid, 256>>>(h2_ptr, offL[0], scolL[0], svalL[0], x_ptr);

    // ---- Layer 1 ----
    gemm_kernel<<<gemm_grid, 256, gemm_smem>>>(x_ptr, W + 128 * 128, b + 128, h2_ptr);
    if (s_async_ok) cudaStreamWaitEvent(0, ev_done[1], 0);
    aggregate_kernel<<<agg_grid, 256>>>(h2_ptr, offL[1], scolL[1], svalL[1], out);
}

// round 9
// speedup vs baseline: 1.7134x; 1.0054x over previous
#include <cuda_runtime.h>
#include <cuda_fp16.h>
#include <math.h>

#define N_NODES 50000
#define N_FEAT  128
#define N_EDGES 800000

#define SCAN_B   512
#define SCAN_NB  ((N_NODES + SCAN_B - 1) / SCAN_B)   // 98

// ---- Scratch (allocation-free rule: __device__ globals) ----
__device__ uint2 g_h2[N_NODES * 32];          // H in half2 pairs: 128 half/row = 32 uint2
__device__ float g_x[N_NODES * N_FEAT];       // layer-0 activation
__device__ int   g_cnt [2][N_NODES];
__device__ int   g_off [2][N_NODES + 1];      // +1: sentinel end = N_EDGES
__device__ int   g_cur [2][N_NODES];
__device__ int   g_bsum[2][128];
__device__ int   g_scol[2][N_EDGES];
__device__ float g_sval[2][N_EDGES];

// ---- Streams/events for capture-time fork/join (created once) ----
static cudaStream_t s_csr[2];
static cudaEvent_t  ev_fork, ev_done[2];
static bool s_async_ok = false;
struct AsyncInit {
    AsyncInit() {
        bool ok = true;
        ok &= cudaStreamCreateWithFlags(&s_csr[0], cudaStreamNonBlocking) == cudaSuccess;
        ok &= cudaStreamCreateWithFlags(&s_csr[1], cudaStreamNonBlocking) == cudaSuccess;
        ok &= cudaEventCreateWithFlags(&ev_fork,    cudaEventDisableTiming) == cudaSuccess;
        ok &= cudaEventCreateWithFlags(&ev_done[0], cudaEventDisableTiming) == cudaSuccess;
        ok &= cudaEventCreateWithFlags(&ev_done[1], cudaEventDisableTiming) == cudaSuccess;
        s_async_ok = ok;
    }
};
static AsyncInit s_async_init;

// ---------------------------------------------------------------------------
// GEMM: H[n][j] = sum_k X[n][k] * W[k][j] + B[j], output stored as half2.
// 64x128 tile, full K in smem (96 KB). fp32 accumulate; fp16 only on store.
// ---------------------------------------------------------------------------
__global__ __launch_bounds__(256) void gemm_kernel(
    const float* __restrict__ X, const float* __restrict__ W,
    const float* __restrict__ B, uint2* __restrict__ H2)
{
    extern __shared__ float smem[];
    float* As = smem;               // [64][128]
    float* Ws = smem + 64 * 128;    // [128][128]
    float4* As4 = (float4*)As;

    const int tid = threadIdx.x;
    const int rowBase = blockIdx.x * 64;

    const float4* W4 = (const float4*)W;
    float4* Ws4 = (float4*)Ws;
    #pragma unroll
    for (int i = tid; i < 128 * 32; i += 256) Ws4[i] = W4[i];

    #pragma unroll
    for (int i = tid; i < 64 * 32; i += 256) {
        int r = i >> 5, c4 = i & 31;
        int gr = rowBase + r;
        float4 v = make_float4(0.f, 0.f, 0.f, 0.f);
        if (gr < N_NODES) v = ((const float4*)X)[gr * 32 + c4];
        As4[i] = v;
    }
    __syncthreads();

    const int warp = tid >> 5, lane = tid & 31;
    const int r0 = warp * 8;
    const int c0 = lane * 4;

    float acc[8][4];
    #pragma unroll
    for (int i = 0; i < 8; i++)
        #pragma unroll
        for (int j = 0; j < 4; j++) acc[i][j] = 0.f;

    #pragma unroll 2
    for (int k4 = 0; k4 < 32; k4++) {
        float4 a[8];
        #pragma unroll
        for (int i = 0; i < 8; i++) a[i] = As4[(r0 + i) * 32 + k4];  // broadcast

        #pragma unroll
        for (int kk = 0; kk < 4; kk++) {
            float4 w = *(const float4*)&Ws[(k4 * 4 + kk) * 128 + c0];
            #pragma unroll
            for (int i = 0; i < 8; i++) {
                float av = (kk == 0) ? a[i].x : (kk == 1) ? a[i].y
                         : (kk == 2) ? a[i].z : a[i].w;
                acc[i][0] += av * w.x;
                acc[i][1] += av * w.y;
                acc[i][2] += av * w.z;
                acc[i][3] += av * w.w;
            }
        }
    }

    float4 bb = *(const float4*)&B[c0];
    #pragma unroll
    for (int i = 0; i < 8; i++) {
        int gr = rowBase + r0 + i;
        if (gr < N_NODES) {
            __half2 h0 = __floats2half2_rn(acc[i][0] + bb.x, acc[i][1] + bb.y);
            __half2 h1 = __floats2half2_rn(acc[i][2] + bb.z, acc[i][3] + bb.w);
            uint2 u;
            u.x = *reinterpret_cast<unsigned*>(&h0);
            u.y = *reinterpret_cast<unsigned*>(&h1);
            H2[gr * 32 + (c0 >> 2)] = u;
        }
    }
}

// ---------------------------------------------------------------------------
// CSR build: histogram -> 3-kernel exclusive scan -> bucket (counting sort)
// ---------------------------------------------------------------------------
__global__ __launch_bounds__(256) void hist_kernel(
    const int* __restrict__ rows, int* __restrict__ cnt)
{
    int e = blockIdx.x * blockDim.x + threadIdx.x;
    if (e < N_EDGES) atomicAdd(&cnt[rows[e]], 1);
}

__global__ __launch_bounds__(SCAN_B) void scan1_kernel(
    const int* __restrict__ cnt, int* __restrict__ off, int* __restrict__ bsum)
{
    __shared__ int s[SCAN_B];
    int i = blockIdx.x * SCAN_B + threadIdx.x;
    int v = (i < N_NODES) ? cnt[i] : 0;
    s[threadIdx.x] = v;
    __syncthreads();
    #pragma unroll
    for (int d = 1; d < SCAN_B; d <<= 1) {
        int t = (threadIdx.x >= d) ? s[threadIdx.x - d] : 0;
        __syncthreads();
        s[threadIdx.x] += t;
        __syncthreads();
    }
    if (i < N_NODES) off[i] = s[threadIdx.x] - v;       // exclusive in-block
    if (threadIdx.x == SCAN_B - 1) bsum[blockIdx.x] = s[SCAN_B - 1];
}

__global__ __launch_bounds__(128) void scan2_kernel(int* __restrict__ bsum)
{
    __shared__ int s[128];
    int t = threadIdx.x;
    int v = (t < SCAN_NB) ? bsum[t] : 0;
    s[t] = v;
    __syncthreads();
    #pragma unroll
    for (int d = 1; d < 128; d <<= 1) {
        int u = (t >= d) ? s[t - d] : 0;
        __syncthreads();
        s[t] += u;
        __syncthreads();
    }
    if (t < SCAN_NB) bsum[t] = s[t] - v;                // exclusive
}

__global__ __launch_bounds__(SCAN_B) void scan3_kernel(
    int* __restrict__ off, const int* __restrict__ bsum, int* __restrict__ cur)
{
    int i = blockIdx.x * SCAN_B + threadIdx.x;
    if (i < N_NODES) {
        int o = off[i] + bsum[blockIdx.x];
        off[i] = o;
        cur[i] = o;
    }
    if (i == 0) off[N_NODES] = N_EDGES;                 // sentinel
}

__global__ __launch_bounds__(256) void bucket_kernel(
    const int* __restrict__ rows, const int* __restrict__ cols,
    const float* __restrict__ vals, int* __restrict__ cur,
    int* __restrict__ scol, float* __restrict__ sval)
{
    int e = blockIdx.x * blockDim.x + threadIdx.x;
    if (e < N_EDGES) {
        int p = atomicAdd(&cur[rows[e]], 1);
        scol[p] = cols[e];
        sval[p] = vals[e];
    }
}

// ---------------------------------------------------------------------------
// Aggregate: one warp per node; gathers half2 H rows (8B/lane), accumulates
// fp32, fused ELU. No atomics, no output memset.
// ---------------------------------------------------------------------------
__global__ __launch_bounds__(256) void aggregate_kernel(
    const uint2* __restrict__ H2, const int* __restrict__ off,
    const int* __restrict__ scol, const float* __restrict__ sval,
    float* __restrict__ out)
{
    int w = (blockIdx.x * blockDim.x + threadIdx.x) >> 5;
    int lane = threadIdx.x & 31;
    if (w >= N_NODES) return;

    int beg = off[w];
    int end = off[w + 1];

    float4 acc = make_float4(0.f, 0.f, 0.f, 0.f);
    #pragma unroll 4
    for (int j = beg; j < end; j++) {
        int   c = scol[j];             // warp-uniform broadcast load
        float v = sval[j];
        uint2 u = H2[c * 32 + lane];
        __half2 p0 = *reinterpret_cast<__half2*>(&u.x);
        __half2 p1 = *reinterpret_cast<__half2*>(&u.y);
        float2 f0 = __half22float2(p0);
        float2 f1 = __half22float2(p1);
        acc.x += v * f0.x;
        acc.y += v * f0.y;
        acc.z += v * f1.x;
        acc.w += v * f1.y;
    }
    acc.x = acc.x > 0.f ? acc.x : expm1f(acc.x);
    acc.y = acc.y > 0.f ? acc.y : expm1f(acc.y);
    acc.z = acc.z > 0.f ? acc.z : expm1f(acc.z);
    acc.w = acc.w > 0.f ? acc.w : expm1f(acc.w);
    ((float4*)out)[w * 32 + lane] = acc;
}

extern "C" void kernel_launch(void* const* d_in, const int* in_sizes, int n_in,
                              void* d_out, int out_size)
{
    const float* x    = (const float*)d_in[0];   // [50000,128]
    const float* W    = (const float*)d_in[1];   // [2,128,128]
    const float* b    = (const float*)d_in[2];   // [2,128]
    const int*   rows = (const int*)d_in[3];     // [2,800000]
    const int*   cols = (const int*)d_in[4];     // [2,800000]
    const float* vals = (const float*)d_in[5];   // [2,800000]
    float* out = (float*)d_out;                  // [50000,128]

    uint2* h2_ptr;
    float* x_ptr;
    int *cnt_b, *off_b, *cur_b, *bsum_b, *scol_b;
    float *sval_b;
    cudaGetSymbolAddress((void**)&h2_ptr, g_h2);
    cudaGetSymbolAddress((void**)&x_ptr,  g_x);
    cudaGetSymbolAddress((void**)&cnt_b,  g_cnt);
    cudaGetSymbolAddress((void**)&off_b,  g_off);
    cudaGetSymbolAddress((void**)&cur_b,  g_cur);
    cudaGetSymbolAddress((void**)&bsum_b, g_bsum);
    cudaGetSymbolAddress((void**)&scol_b, g_scol);
    cudaGetSymbolAddress((void**)&sval_b, g_sval);

    const int gemm_smem = (64 * 128 + 128 * 128) * sizeof(float);  // 96 KB
    cudaFuncSetAttribute(gemm_kernel,
                         cudaFuncAttributeMaxDynamicSharedMemorySize, gemm_smem);

    const int gemm_grid = (N_NODES + 63) / 64;
    const int edge_grid = (N_EDGES + 255) / 256;
    const int agg_grid  = (N_NODES * 32 + 255) / 256;   // warp per node

    int*   cntL[2]  = {cnt_b,  cnt_b  + N_NODES};
    int*   offL[2]  = {off_b,  off_b  + (N_NODES + 1)};
    int*   curL[2]  = {cur_b,  cur_b  + N_NODES};
    int*   bsumL[2] = {bsum_b, bsum_b + 128};
    int*   scolL[2] = {scol_b, scol_b + N_EDGES};
    float* svalL[2] = {sval_b, sval_b + N_EDGES};

    // ---- CSR builds for both layers (depend only on edge inputs) ----
    if (s_async_ok) {
        cudaEventRecord(ev_fork, 0);
        for (int l = 0; l < 2; l++) {
            cudaStream_t s = s_csr[l];
            const int* rl = rows + (size_t)l * N_EDGES;
            cudaStreamWaitEvent(s, ev_fork, 0);
            cudaMemsetAsync(cntL[l], 0, N_NODES * sizeof(int), s);
            hist_kernel <<<edge_grid, 256, 0, s>>>(rl, cntL[l]);
            scan1_kernel<<<SCAN_NB, SCAN_B, 0, s>>>(cntL[l], offL[l], bsumL[l]);
            scan2_kernel<<<1, 128, 0, s>>>(bsumL[l]);
            scan3_kernel<<<SCAN_NB, SCAN_B, 0, s>>>(offL[l], bsumL[l], curL[l]);
            bucket_kernel<<<edge_grid, 256, 0, s>>>(
                rl, cols + (size_t)l * N_EDGES, vals + (size_t)l * N_EDGES,
                curL[l], scolL[l], svalL[l]);
            cudaEventRecord(ev_done[l], s);
        }
    } else {
        for (int l = 0; l < 2; l++) {
            const int* rl = rows + (size_t)l * N_EDGES;
            cudaMemsetAsync(cntL[l], 0, N_NODES * sizeof(int));
            hist_kernel <<<edge_grid, 256>>>(rl, cntL[l]);
            scan1_kernel<<<SCAN_NB, SCAN_B>>>(cntL[l], offL[l], bsumL[l]);
            scan2_kernel<<<1, 128>>>(bsumL[l]);
            scan3_kernel<<<SCAN_NB, SCAN_B>>>(offL[l], bsumL[l], curL[l]);
            bucket_kernel<<<edge_grid, 256>>>(
                rl, cols + (size_t)l * N_EDGES, vals + (size_t)l * N_EDGES,
                curL[l], scolL[l], svalL[l]);
        }
    }

    // ---- Layer 0 ----
    gemm_kernel<<<gemm_grid, 256, gemm_smem>>>(x, W, b, h2_ptr);
    if (s_async_ok) cudaStreamWaitEvent(0, ev_done[0], 0);
    aggregate_kernel<<<agg_grid, 256>>>(h2_ptr, offL[0], scolL[0], svalL[0], x_ptr);

    // ---- Layer 1 ----
    gemm_kernel<<<gemm_grid, 256, gemm_smem>>>(x_ptr, W + 128 * 128, b + 128, h2_ptr);
    if (s_async_ok) cudaStreamWaitEvent(0, ev_done[1], 0);
    aggregate_kernel<<<agg_grid, 256>>>(h2_ptr, offL[1], scolL[1], svalL[1], out);
}